// round 12
// baseline (speedup 1.0000x reference)
#include <cuda_runtime.h>
#include <cuda_fp16.h>
#include <math.h>
#include <stdint.h>

// ---------------------------------------------------------------------------
// AttSRU: T=512, B=32, S=512, D=512, fp32 I/O.
// Round 12: warp-per-row LN/softmax/final (no block barriers), fp16 mma GEMMs,
// all-fp16 intermediates. 1/sqrt(D) folded into align GEMM alpha.
// ---------------------------------------------------------------------------

namespace {
constexpr int  kT = 512, kB = 32, kS = 512, kD = 512;
constexpr long kTB   = (long)kT * kB;      // 16384 rows
constexpr long kTBD  = kTB * kD;           // 8388608
constexpr float kEPS = 1e-6f;

// fp16 scratch offsets (halfs)
constexpr long HF_PREV  = 0;
constexpr long HF_ENC   = HF_PREV  + kTBD;
constexpr long HF_PCTXR = HF_ENC   + kTBD;
constexpr long HF_PCTX  = HF_PCTXR + kTBD;
constexpr long HF_PCTXT = HF_PCTX  + kTBD;
constexpr long HF_SS    = HF_PCTXT + kTBD;
constexpr long HF_ATTR  = HF_SS    + kTBD;
constexpr long HF_ATT   = HF_ATTR  + kTBD;
constexpr long HF_SC    = HF_ATT   + kTBD;   // align scores (pre-scaled)
constexpr long HF_AV    = HF_SC    + kTBD;
constexpr long HF_AO    = HF_AV    + kTBD;
constexpr long HF_H1    = HF_AO    + kTBD;
constexpr long HF_H2    = HF_H1    + kTBD;
constexpr long HF_Z     = HF_H2    + kTBD;
constexpr long HF_HG    = HF_Z     + kTBD;
constexpr long HF_PL    = HF_HG    + kTBD;
constexpr long HF_PRE   = HF_PL    + kTBD;   // [TB,3D]
constexpr long HF_WTIN  = HF_PRE   + 3 * kTBD;
constexpr long HF_WTENC = HF_WTIN  + (long)3 * kD * kD;
constexpr long HF_WTATT = HF_WTENC + (long)kD * kD;
constexpr long HF_WTHID = HF_WTATT + (long)kD * kD;
constexpr long HF_WTCTX = HF_WTHID + (long)kD * kD;
constexpr long kSCH     = HF_WTCTX + (long)kD * kD;

constexpr long kSCF = (long)kB * kD;          // final scan state (fp32)

// fp16 GEMM smem: K-chunk 32 halfs/row, row stride 40 halfs (80B)
constexpr int RSH = 40;
constexpr int OPH = 128 * RSH;
constexpr int STG = 2 * OPH;
constexpr int GEMM_SMEM = 3 * STG * 2;        // 61440 B -> 2 CTAs/SM
}

__device__ float  g_scf[kSCF];
__device__ __half g_sch[kSCH];

// ---------------------------------------------------------------------------
// Helpers
// ---------------------------------------------------------------------------
__device__ __forceinline__ float warpSum(float v) {
#pragma unroll
    for (int o = 16; o; o >>= 1) v += __shfl_xor_sync(0xffffffffu, v, o);
    return v;
}
__device__ __forceinline__ float warpMax(float v) {
#pragma unroll
    for (int o = 16; o; o >>= 1) v = fmaxf(v, __shfl_xor_sync(0xffffffffu, v, o));
    return v;
}
__device__ __forceinline__ float sigm(float x) { return 1.f / (1.f + expf(-x)); }

// unpack 8 halfs (uint4) -> 8 floats
__device__ __forceinline__ void up8(uint4 u, float* f) {
    const __half2* h = reinterpret_cast<const __half2*>(&u);
#pragma unroll
    for (int k = 0; k < 4; k++) {
        float2 t = __half22float2(h[k]);
        f[2 * k] = t.x; f[2 * k + 1] = t.y;
    }
}
// pack 8 floats -> uint4 of halfs
__device__ __forceinline__ uint4 pk8(const float* f) {
    uint4 u;
    __half2* h = reinterpret_cast<__half2*>(&u);
#pragma unroll
    for (int k = 0; k < 4; k++) h[k] = __floats2half2_rn(f[2 * k], f[2 * k + 1]);
    return u;
}

__device__ __forceinline__ void ldsm4(uint32_t& r0, uint32_t& r1,
                                      uint32_t& r2, uint32_t& r3, uint32_t addr) {
    asm volatile("ldmatrix.sync.aligned.m8n8.x4.shared.b16 {%0,%1,%2,%3}, [%4];"
                 : "=r"(r0), "=r"(r1), "=r"(r2), "=r"(r3) : "r"(addr));
}

// ---------------------------------------------------------------------------
// fp16 mma GEMM: C[M,N] = alpha * A[M,K] @ B[N,K]^T  (fp32 accum, fp16 out)
// Grid: (N/128, M/128, batch). Block: 256 (8 warps 4x2, warp tile 32x64).
// ---------------------------------------------------------------------------
__global__ __launch_bounds__(256, 2)
void gemm_h_kernel(const __half* __restrict__ A, const __half* __restrict__ B,
                   __half* __restrict__ C, int K,
                   long lda, long ldb, long ldc,
                   long sA, long sB, long sC, float alpha)
{
    extern __shared__ __half smh[];
    const uint32_t sb = (uint32_t)__cvta_generic_to_shared(smh);
    A += (long)blockIdx.z * sA;
    B += (long)blockIdx.z * sB;
    C += (long)blockIdx.z * sC;
    const int bm = blockIdx.y * 128, bn = blockIdx.x * 128;
    const int tid = threadIdx.x, wid = tid >> 5, lane = tid & 31;
    const int mw = (wid >> 1) * 32, nw = (wid & 1) * 64;
    const int lr = lane >> 2, lc = lane & 3;

    const int aoff = (mw + (lane & 15)) * RSH + (lane >> 4) * 8;
    const int boff0 = OPH + (nw + (lane & 7) + (lane >> 4) * 8) * RSH
                    + ((lane >> 3) & 1) * 8;

    const __half* gp[4];
    uint32_t dsto[4];
#pragma unroll
    for (int i = 0; i < 4; i++) {
        int id = tid + i * 256;
        bool isA = id < 512;
        int rid = id & 511;
        int row = rid >> 2, q = rid & 3;
        gp[i] = (isA ? A + (long)(bm + row) * lda
                     : B + (long)(bn + row) * ldb) + q * 8;
        dsto[i] = (isA ? 0u : (uint32_t)OPH) + (uint32_t)(row * RSH + q * 8);
    }
    const int nch = K >> 5;

    auto load_chunk = [&](int c, int s) {
        long ko = (long)c * 32;
        uint32_t base = (uint32_t)(s * STG);
#pragma unroll
        for (int i = 0; i < 4; i++) {
            uint32_t d = sb + (base + dsto[i]) * 2u;
            asm volatile("cp.async.cg.shared.global [%0], [%1], 16;"
                         :: "r"(d), "l"(gp[i] + ko));
        }
    };

    float acc[2][8][4];
#pragma unroll
    for (int i = 0; i < 2; i++)
#pragma unroll
        for (int j = 0; j < 8; j++)
#pragma unroll
            for (int v = 0; v < 4; v++) acc[i][j][v] = 0.f;

    load_chunk(0, 0);
    asm volatile("cp.async.commit_group;");
    if (nch > 1) {
        load_chunk(1, 1);
        asm volatile("cp.async.commit_group;");
    }

    for (int c = 0; c < nch; c++) {
        if (c + 1 < nch) asm volatile("cp.async.wait_group 1;");
        else             asm volatile("cp.async.wait_group 0;");
        __syncthreads();
        if (c + 2 < nch) {
            load_chunk(c + 2, (c + 2) % 3);
            asm volatile("cp.async.commit_group;");
        }
        const uint32_t stb = sb + (uint32_t)((c % 3) * STG) * 2u;
#pragma unroll
        for (int ks = 0; ks < 2; ks++) {
            const uint32_t kb = (uint32_t)(ks * 16) * 2u;
            uint32_t a[2][4];
#pragma unroll
            for (int im = 0; im < 2; im++)
                ldsm4(a[im][0], a[im][1], a[im][2], a[im][3],
                      stb + (uint32_t)(aoff + im * 16 * RSH) * 2u + kb);
#pragma unroll
            for (int p = 0; p < 4; p++) {
                uint32_t b0, b1, b2, b3;
                ldsm4(b0, b1, b2, b3, stb + (uint32_t)(boff0 + p * 16 * RSH) * 2u + kb);
#pragma unroll
                for (int im = 0; im < 2; im++) {
                    asm volatile(
                        "mma.sync.aligned.m16n8k16.row.col.f32.f16.f16.f32 "
                        "{%0,%1,%2,%3}, {%4,%5,%6,%7}, {%8,%9}, {%0,%1,%2,%3};"
                        : "+f"(acc[im][2 * p][0]), "+f"(acc[im][2 * p][1]),
                          "+f"(acc[im][2 * p][2]), "+f"(acc[im][2 * p][3])
                        : "r"(a[im][0]), "r"(a[im][1]), "r"(a[im][2]), "r"(a[im][3]),
                          "r"(b0), "r"(b1));
                    asm volatile(
                        "mma.sync.aligned.m16n8k16.row.col.f32.f16.f16.f32 "
                        "{%0,%1,%2,%3}, {%4,%5,%6,%7}, {%8,%9}, {%0,%1,%2,%3};"
                        : "+f"(acc[im][2 * p + 1][0]), "+f"(acc[im][2 * p + 1][1]),
                          "+f"(acc[im][2 * p + 1][2]), "+f"(acc[im][2 * p + 1][3])
                        : "r"(a[im][0]), "r"(a[im][1]), "r"(a[im][2]), "r"(a[im][3]),
                          "r"(b2), "r"(b3));
                }
            }
        }
    }

#pragma unroll
    for (int im = 0; im < 2; im++) {
        long r0 = (long)(bm + mw + im * 16 + lr);
#pragma unroll
        for (int jn = 0; jn < 8; jn++) {
            long col = bn + nw + jn * 8 + lc * 2;
            *reinterpret_cast<__half2*>(C + r0 * ldc + col) =
                __floats2half2_rn(acc[im][jn][0] * alpha, acc[im][jn][1] * alpha);
            *reinterpret_cast<__half2*>(C + (r0 + 8) * ldc + col) =
                __floats2half2_rn(acc[im][jn][2] * alpha, acc[im][jn][3] * alpha);
        }
    }
}

// ---------------------------------------------------------------------------
// fp32 -> fp16 convert
// ---------------------------------------------------------------------------
__global__ void f2h_kernel(const float* __restrict__ in, __half* __restrict__ out,
                           long n4)
{
    long i = (long)blockIdx.x * blockDim.x + threadIdx.x;
    if (i >= n4) return;
    float4 v = reinterpret_cast<const float4*>(in)[i];
    reinterpret_cast<__half2*>(out)[i * 2]     = __floats2half2_rn(v.x, v.y);
    reinterpret_cast<__half2*>(out)[i * 2 + 1] = __floats2half2_rn(v.z, v.w);
}

// ---------------------------------------------------------------------------
// Transposes
// ---------------------------------------------------------------------------
__global__ void transpose_f2h_kernel(const float* __restrict__ in,
                                     __half* __restrict__ out,
                                     int R, int C, long sIn, long sOut)
{
    __shared__ float t[32][33];
    in  += (long)blockIdx.z * sIn;
    out += (long)blockIdx.z * sOut;
    int bx = blockIdx.x * 32, by = blockIdx.y * 32;
    int x = threadIdx.x, y = threadIdx.y;
#pragma unroll
    for (int i = 0; i < 32; i += 8) t[y + i][x] = in[(long)(by + y + i) * C + bx + x];
    __syncthreads();
#pragma unroll
    for (int i = 0; i < 32; i += 8)
        out[(long)(bx + y + i) * R + by + x] = __float2half_rn(t[x][y + i]);
}

__global__ void transpose4_f2h_kernel(const float* __restrict__ w0, const float* __restrict__ w1,
                                      const float* __restrict__ w2, const float* __restrict__ w3,
                                      __half* __restrict__ o0, __half* __restrict__ o1,
                                      __half* __restrict__ o2, __half* __restrict__ o3)
{
    __shared__ float t[32][33];
    const float* in; __half* out;
    switch (blockIdx.z) {
        case 0: in = w0; out = o0; break;
        case 1: in = w1; out = o1; break;
        case 2: in = w2; out = o2; break;
        default: in = w3; out = o3; break;
    }
    int bx = blockIdx.x * 32, by = blockIdx.y * 32;
    int x = threadIdx.x, y = threadIdx.y;
#pragma unroll
    for (int i = 0; i < 32; i += 8) t[y + i][x] = in[(long)(by + y + i) * kD + bx + x];
    __syncthreads();
#pragma unroll
    for (int i = 0; i < 32; i += 8)
        out[(long)(bx + y + i) * kD + by + x] = __float2half_rn(t[x][y + i]);
}

__global__ void transpose_h2h_kernel(const __half* __restrict__ in,
                                     __half* __restrict__ out,
                                     int R, int C, long sIn, long sOut)
{
    __shared__ __half t[32][34];
    in  += (long)blockIdx.z * sIn;
    out += (long)blockIdx.z * sOut;
    int bx = blockIdx.x * 32, by = blockIdx.y * 32;
    int x = threadIdx.x, y = threadIdx.y;
#pragma unroll
    for (int i = 0; i < 32; i += 8) t[y + i][x] = in[(long)(by + y + i) * C + bx + x];
    __syncthreads();
#pragma unroll
    for (int i = 0; i < 32; i += 8)
        out[(long)(bx + y + i) * R + by + x] = t[x][y + i];
}

// ---------------------------------------------------------------------------
// Warp-per-row LN over 3D=1536 (fp16 in), split + sigmoid -> Z / HG / PL.
// Block 256 = 8 warps = 8 rows; grid = TB/8. Lane owns halfs lane*8 + k*256.
// ---------------------------------------------------------------------------
__global__ __launch_bounds__(256)
void ln_preact_kernel(const __half* __restrict__ pre,
                      const float* __restrict__ g, const float* __restrict__ bb,
                      __half* __restrict__ Z, __half* __restrict__ HG,
                      __half* __restrict__ PL)
{
    int warp = threadIdx.x >> 5, lane = threadIdx.x & 31;
    long row = (long)blockIdx.x * 8 + warp;
    const __half* r = pre + row * (3 * kD) + lane * 8;
    uint4 u[6];
#pragma unroll
    for (int k = 0; k < 6; k++) u[k] = *reinterpret_cast<const uint4*>(r + k * 256);
    float s = 0.f, q = 0.f;
#pragma unroll
    for (int k = 0; k < 6; k++) {
        float f[8];
        up8(u[k], f);
#pragma unroll
        for (int i = 0; i < 8; i++) { s += f[i]; q += f[i] * f[i]; }
    }
    s = warpSum(s);
    q = warpSum(q);
    const float invW = 1.f / (3 * kD);
    float m  = s * invW;
    float rv = rsqrtf(q * invW - m * m + kEPS);
    long rD = row * kD;
#pragma unroll
    for (int k = 0; k < 6; k++) {
        int c = k * 256 + lane * 8;
        float f[8], o[8];
        up8(u[k], f);
        float4 g0 = *reinterpret_cast<const float4*>(g + c);
        float4 g1 = *reinterpret_cast<const float4*>(g + c + 4);
        float4 b0 = *reinterpret_cast<const float4*>(bb + c);
        float4 b1 = *reinterpret_cast<const float4*>(bb + c + 4);
        const float* gv = &g0.x;  // g0,g1 contiguous on stack? avoid: index manually
        o[0] = g0.x * ((f[0] - m) * rv) + b0.x;
        o[1] = g0.y * ((f[1] - m) * rv) + b0.y;
        o[2] = g0.z * ((f[2] - m) * rv) + b0.z;
        o[3] = g0.w * ((f[3] - m) * rv) + b0.w;
        o[4] = g1.x * ((f[4] - m) * rv) + b1.x;
        o[5] = g1.y * ((f[5] - m) * rv) + b1.y;
        o[6] = g1.z * ((f[6] - m) * rv) + b1.z;
        o[7] = g1.w * ((f[7] - m) * rv) + b1.w;
        (void)gv;
        if (k < 2) {
#pragma unroll
            for (int i = 0; i < 8; i++) o[i] = sigm(o[i]);
            *reinterpret_cast<uint4*>(Z + rD + c) = pk8(o);
        } else if (k < 4) {
#pragma unroll
            for (int i = 0; i < 8; i++) o[i] = sigm(o[i]);
            *reinterpret_cast<uint4*>(HG + rD + c - kD) = pk8(o);
        } else {
            *reinterpret_cast<uint4*>(PL + rD + c - 2 * kD) = pk8(o);
        }
    }
}

// Warp-per-row LN over D=512: fp16 -> fp16. Block 256 = 8 rows, grid TB/8.
__global__ __launch_bounds__(256)
void ln512w_kernel(const __half* __restrict__ x, __half* __restrict__ out,
                   const float* __restrict__ g, const float* __restrict__ b)
{
    int warp = threadIdx.x >> 5, lane = threadIdx.x & 31;
    long row = (long)blockIdx.x * 8 + warp;
    const __half* r = x + row * kD + lane * 8;
    uint4 u0 = *reinterpret_cast<const uint4*>(r);
    uint4 u1 = *reinterpret_cast<const uint4*>(r + 256);
    float f[16];
    up8(u0, f);
    up8(u1, f + 8);
    float s = 0.f, q = 0.f;
#pragma unroll
    for (int i = 0; i < 16; i++) { s += f[i]; q += f[i] * f[i]; }
    s = warpSum(s);
    q = warpSum(q);
    const float invW = 1.f / kD;
    float m  = s * invW;
    float rv = rsqrtf(q * invW - m * m + kEPS);
    float o[16];
#pragma unroll
    for (int seg = 0; seg < 2; seg++) {
        int c = seg * 256 + lane * 8;
        float4 g0 = *reinterpret_cast<const float4*>(g + c);
        float4 g1 = *reinterpret_cast<const float4*>(g + c + 4);
        float4 b0 = *reinterpret_cast<const float4*>(b + c);
        float4 b1 = *reinterpret_cast<const float4*>(b + c + 4);
        float* oo = o + seg * 8;
        const float* ff = f + seg * 8;
        oo[0] = g0.x * ((ff[0] - m) * rv) + b0.x;
        oo[1] = g0.y * ((ff[1] - m) * rv) + b0.y;
        oo[2] = g0.z * ((ff[2] - m) * rv) + b0.z;
        oo[3] = g0.w * ((ff[3] - m) * rv) + b0.w;
        oo[4] = g1.x * ((ff[4] - m) * rv) + b1.x;
        oo[5] = g1.y * ((ff[5] - m) * rv) + b1.y;
        oo[6] = g1.z * ((ff[6] - m) * rv) + b1.z;
        oo[7] = g1.w * ((ff[7] - m) * rv) + b1.w;
    }
    __half* w = out + row * kD + lane * 8;
    *reinterpret_cast<uint4*>(w)       = pk8(o);
    *reinterpret_cast<uint4*>(w + 256) = pk8(o + 8);
}

// SRU scan over half2 lanes: fp32 state, fp16 ss out, fp32 final state.
__global__ __launch_bounds__(64)
void scan_kernel(const __half2* __restrict__ Z, const __half2* __restrict__ PL,
                 const float* __restrict__ h0, __half2* __restrict__ ssh,
                 float* __restrict__ sslast)
{
    constexpr int BATCH = 16;
    int idx = blockIdx.x * 64 + threadIdx.x;
    float2 s = reinterpret_cast<const float2*>(h0)[idx];
    const long stride = (long)kB * kD / 2;
    long off = idx;
    for (int g = 0; g < kT / BATCH; g++) {
        __half2 z[BATCH], p[BATCH];
#pragma unroll
        for (int j = 0; j < BATCH; j++) z[j] = Z[off + j * stride];
#pragma unroll
        for (int j = 0; j < BATCH; j++) p[j] = PL[off + j * stride];
#pragma unroll
        for (int j = 0; j < BATCH; j++) {
            float2 zf = __half22float2(z[j]);
            float2 pf = __half22float2(p[j]);
            s.x = (1.f - zf.x) * s.x + zf.x * pf.x;
            s.y = (1.f - zf.y) * s.y + zf.y * pf.y;
            ssh[off + j * stride] = __floats2half2_rn(s.x, s.y);
        }
        off += (long)BATCH * stride;
    }
    reinterpret_cast<float2*>(sslast)[idx] = s;
}

// Warp-per-row masked softmax over S=512 (scores pre-scaled by 1/sqrt(D)).
// Block 256 = 8 rows, grid (B*T)/8. Writes fp32 p_attn + fp16 probs.
__global__ __launch_bounds__(256)
void softmaxw_kernel(const __half* __restrict__ sc, __half* __restrict__ avh,
                     float* __restrict__ pattn, const int* __restrict__ mlen)
{
    int warp = threadIdx.x >> 5, lane = threadIdx.x & 31;
    long row = (long)blockIdx.x * 8 + warp;      // b*T + t
    int b = (int)(row >> 9), t = (int)(row & 511);
    int ml = mlen[b];
    const __half* r = sc + row * kS + lane * 8;
    uint4 u0 = *reinterpret_cast<const uint4*>(r);
    uint4 u1 = *reinterpret_cast<const uint4*>(r + 256);
    float f[16];
    up8(u0, f);
    up8(u1, f + 8);
    int c0 = lane * 8, c1 = 256 + lane * 8;
    float mx = -INFINITY;
#pragma unroll
    for (int i = 0; i < 8; i++) {
        if (c0 + i < ml) mx = fmaxf(mx, f[i]);
        if (c1 + i < ml) mx = fmaxf(mx, f[8 + i]);
    }
    mx = warpMax(mx);
    float e[16];
    float sum = 0.f;
#pragma unroll
    for (int i = 0; i < 8; i++) {
        e[i]     = (c0 + i < ml) ? expf(f[i] - mx)     : 0.f;
        e[8 + i] = (c1 + i < ml) ? expf(f[8 + i] - mx) : 0.f;
        sum += e[i] + e[8 + i];
    }
    sum = warpSum(sum);
    float is = 1.f / sum;
#pragma unroll
    for (int i = 0; i < 16; i++) e[i] *= is;
    float* pa = pattn + ((long)t * kB + b) * kS;
    *reinterpret_cast<float4*>(pa + c0)     = make_float4(e[0], e[1], e[2], e[3]);
    *reinterpret_cast<float4*>(pa + c0 + 4) = make_float4(e[4], e[5], e[6], e[7]);
    *reinterpret_cast<float4*>(pa + c1)     = make_float4(e[8], e[9], e[10], e[11]);
    *reinterpret_cast<float4*>(pa + c1 + 4) = make_float4(e[12], e[13], e[14], e[15]);
    __half* w = avh + row * kS + lane * 8;
    *reinterpret_cast<uint4*>(w)       = pk8(e);
    *reinterpret_cast<uint4*>(w + 256) = pk8(e + 8);
}

// Warp-per-row final: out = (1-hg)*tanh(LN(h1)+LN(h2)) + hg*prev.
// Block 256 = 8 rows, grid TB/8.
__global__ __launch_bounds__(256)
void finalw_kernel(const __half* __restrict__ h1, const __half* __restrict__ h2,
                   const __half* __restrict__ HG, const float* __restrict__ prev,
                   const float* __restrict__ g_h, const float* __restrict__ b_h,
                   const float* __restrict__ g_c, const float* __restrict__ b_c,
                   float* __restrict__ out)
{
    int warp = threadIdx.x >> 5, lane = threadIdx.x & 31;
    long row = (long)blockIdx.x * 8 + warp;
    long base = row * kD + lane * 8;
    uint4 a0 = *reinterpret_cast<const uint4*>(h1 + base);
    uint4 a1 = *reinterpret_cast<const uint4*>(h1 + base + 256);
    uint4 d0 = *reinterpret_cast<const uint4*>(h2 + base);
    uint4 d1 = *reinterpret_cast<const uint4*>(h2 + base + 256);
    float fa[16], fd[16];
    up8(a0, fa); up8(a1, fa + 8);
    up8(d0, fd); up8(d1, fd + 8);
    float s1 = 0.f, q1 = 0.f, s2 = 0.f, q2 = 0.f;
#pragma unroll
    for (int i = 0; i < 16; i++) {
        s1 += fa[i]; q1 += fa[i] * fa[i];
        s2 += fd[i]; q2 += fd[i] * fd[i];
    }
    s1 = warpSum(s1); q1 = warpSum(q1);
    s2 = warpSum(s2); q2 = warpSum(q2);
    const float invW = 1.f / kD;
    float m1 = s1 * invW, r1 = rsqrtf(q1 * invW - m1 * m1 + kEPS);
    float m2 = s2 * invW, r2 = rsqrtf(q2 * invW - m2 * m2 + kEPS);
    uint4 hg0 = *reinterpret_cast<const uint4*>(HG + base);
    uint4 hg1 = *reinterpret_cast<const uint4*>(HG + base + 256);
    float fh[16];
    up8(hg0, fh); up8(hg1, fh + 8);
#pragma unroll
    for (int seg = 0; seg < 2; seg++) {
        int c = seg * 256 + lane * 8;
        long ob = row * kD + c;
        float4 gh0 = *reinterpret_cast<const float4*>(g_h + c);
        float4 gh1 = *reinterpret_cast<const float4*>(g_h + c + 4);
        float4 bh0 = *reinterpret_cast<const float4*>(b_h + c);
        float4 bh1 = *reinterpret_cast<const float4*>(b_h + c + 4);
        float4 gc0 = *reinterpret_cast<const float4*>(g_c + c);
        float4 gc1 = *reinterpret_cast<const float4*>(g_c + c + 4);
        float4 bc0 = *reinterpret_cast<const float4*>(b_c + c);
        float4 bc1 = *reinterpret_cast<const float4*>(b_c + c + 4);
        float4 pv0 = *reinterpret_cast<const float4*>(prev + ob);
        float4 pv1 = *reinterpret_cast<const float4*>(prev + ob + 4);
        const float* A = fa + seg * 8;
        const float* D = fd + seg * 8;
        const float* H = fh + seg * 8;
        float tv[8];
        tv[0] = tanhf(gh0.x * ((A[0] - m1) * r1) + bh0.x + gc0.x * ((D[0] - m2) * r2) + bc0.x);
        tv[1] = tanhf(gh0.y * ((A[1] - m1) * r1) + bh0.y + gc0.y * ((D[1] - m2) * r2) + bc0.y);
        tv[2] = tanhf(gh0.z * ((A[2] - m1) * r1) + bh0.z + gc0.z * ((D[2] - m2) * r2) + bc0.z);
        tv[3] = tanhf(gh0.w * ((A[3] - m1) * r1) + bh0.w + gc0.w * ((D[3] - m2) * r2) + bc0.w);
        tv[4] = tanhf(gh1.x * ((A[4] - m1) * r1) + bh1.x + gc1.x * ((D[4] - m2) * r2) + bc1.x);
        tv[5] = tanhf(gh1.y * ((A[5] - m1) * r1) + bh1.y + gc1.y * ((D[5] - m2) * r2) + bc1.y);
        tv[6] = tanhf(gh1.z * ((A[6] - m1) * r1) + bh1.z + gc1.z * ((D[6] - m2) * r2) + bc1.z);
        tv[7] = tanhf(gh1.w * ((A[7] - m1) * r1) + bh1.w + gc1.w * ((D[7] - m2) * r2) + bc1.w);
        float4 o0, o1;
        o0.x = (1.f - H[0]) * tv[0] + H[0] * pv0.x;
        o0.y = (1.f - H[1]) * tv[1] + H[1] * pv0.y;
        o0.z = (1.f - H[2]) * tv[2] + H[2] * pv0.z;
        o0.w = (1.f - H[3]) * tv[3] + H[3] * pv0.w;
        o1.x = (1.f - H[4]) * tv[4] + H[4] * pv1.x;
        o1.y = (1.f - H[5]) * tv[5] + H[5] * pv1.y;
        o1.z = (1.f - H[6]) * tv[6] + H[6] * pv1.z;
        o1.w = (1.f - H[7]) * tv[7] + H[7] * pv1.w;
        *reinterpret_cast<float4*>(out + ob)     = o0;
        *reinterpret_cast<float4*>(out + ob + 4) = o1;
    }
}

// ---------------------------------------------------------------------------
// Launch
// ---------------------------------------------------------------------------
extern "C" void kernel_launch(void* const* d_in, const int* in_sizes, int n_in,
                              void* d_out, int out_size)
{
    int i_prev = -1, i_enc = -1, i_hidden = -1, i_ml = -1, i_Win = -1;
    int w4[4] = {-1, -1, -1, -1}; int n4 = 0;
    int p2[2] = {-1, -1};         int np = 0;
    int v8[8] = {-1, -1, -1, -1, -1, -1, -1, -1}; int nv = 0;
    for (int i = 0; i < n_in; i++) {
        switch (in_sizes[i]) {
            case 8388608: if (i_prev < 0) i_prev = i; else i_enc = i; break;
            case 16384:   i_hidden = i; break;
            case 32:      i_ml = i; break;
            case 786432:  i_Win = i; break;
            case 262144:  if (n4 < 4) w4[n4++] = i; break;
            case 1536:    if (np < 2) p2[np++] = i; break;
            case 512:     if (nv < 8) v8[nv++] = i; break;
            default: break;
        }
    }
    const float* prev   = (const float*)d_in[i_prev];
    const float* hidden = (const float*)d_in[i_hidden];
    const float* enc    = (const float*)d_in[i_enc];
    const int*   mlen   = (const int*)d_in[i_ml];
    const float* W_in   = (const float*)d_in[i_Win];
    const float* W_enc  = (const float*)d_in[w4[0]];
    const float* W_att  = (const float*)d_in[w4[1]];
    const float* W_hid  = (const float*)d_in[w4[2]];
    const float* W_ctx  = (const float*)d_in[w4[3]];
    const float* g_pre  = (const float*)d_in[p2[0]];
    const float* b_pre  = (const float*)d_in[p2[1]];
    const float* g_enc  = (const float*)d_in[v8[0]];
    const float* b_enc  = (const float*)d_in[v8[1]];
    const float* g_att  = (const float*)d_in[v8[2]];
    const float* b_att  = (const float*)d_in[v8[3]];
    const float* g_h    = (const float*)d_in[v8[4]];
    const float* b_h    = (const float*)d_in[v8[5]];
    const float* g_c    = (const float*)d_in[v8[6]];
    const float* b_c    = (const float*)d_in[v8[7]];

    float* sf = nullptr;
    __half* sh = nullptr;
    cudaGetSymbolAddress((void**)&sf, g_scf);
    cudaGetSymbolAddress((void**)&sh, g_sch);

    float* out       = (float*)d_out;            // [T,B,D]
    float* out_hid   = out + kTBD;               // [B,D]
    float* out_pattn = out_hid + (long)kB * kD;  // [T,B,S]

    cudaFuncSetAttribute(gemm_h_kernel,
                         cudaFuncAttributeMaxDynamicSharedMemorySize, GEMM_SMEM);

    dim3 tb(32, 8);
    const float invsq = rsqrtf((float)kD);
    const long bDS = (long)kB * kD;

    cudaStream_t s1;
    cudaStreamCreateWithFlags(&s1, cudaStreamNonBlocking);
    cudaEvent_t eW, eP, eS, eH;
    cudaEventCreateWithFlags(&eW, cudaEventDisableTiming);
    cudaEventCreateWithFlags(&eP, cudaEventDisableTiming);
    cudaEventCreateWithFlags(&eS, cudaEventDisableTiming);
    cudaEventCreateWithFlags(&eH, cudaEventDisableTiming);

    // -- side stream: enc convert --
    f2h_kernel<<<8192, 256, 0, s1>>>(enc, sh + HF_ENC, kTBD / 4);

    // -- main: prev convert + weight transposes --
    f2h_kernel<<<8192, 256>>>(prev, sh + HF_PREV, kTBD / 4);
    transpose_f2h_kernel<<<dim3(16, 16, 3), tb>>>(W_in, sh + HF_WTIN, kD, 3 * kD,
                                                  512, (long)kD * kD);
    transpose4_f2h_kernel<<<dim3(16, 16, 4), tb>>>(W_enc, W_att, W_hid, W_ctx,
                                                   sh + HF_WTENC, sh + HF_WTATT,
                                                   sh + HF_WTHID, sh + HF_WTCTX);
    cudaEventRecord(eW, 0);

    // -- side stream: enc chain --
    cudaStreamWaitEvent(s1, eW, 0);
    gemm_h_kernel<<<dim3(4, 128, 1), 256, GEMM_SMEM, s1>>>(
        sh + HF_ENC, sh + HF_WTENC, sh + HF_PCTXR, 512, 512, 512, 512, 0, 0, 0, 1.f);
    ln512w_kernel<<<2048, 256, 0, s1>>>(sh + HF_PCTXR, sh + HF_PCTX, g_enc, b_enc);
    transpose_h2h_kernel<<<dim3(16, 16, 32), tb, 0, s1>>>(
        sh + HF_PCTX, sh + HF_PCTXT, kS, kD, (long)kS * kD, (long)kD * kS);
    cudaEventRecord(eP, s1);

    // -- main: preact chain --
    gemm_h_kernel<<<dim3(12, 128, 1), 256, GEMM_SMEM>>>(
        sh + HF_PREV, sh + HF_WTIN, sh + HF_PRE, 512, 512, 512, 1536, 0, 0, 0, 1.f);
    ln_preact_kernel<<<2048, 256>>>(sh + HF_PRE, g_pre, b_pre,
                                    sh + HF_Z, sh + HF_HG, sh + HF_PL);
    scan_kernel<<<128, 64>>>(reinterpret_cast<__half2*>(sh + HF_Z),
                             reinterpret_cast<__half2*>(sh + HF_PL), hidden,
                             reinterpret_cast<__half2*>(sh + HF_SS), sf);
    cudaEventRecord(eS, 0);
    gemm_h_kernel<<<dim3(4, 128, 1), 256, GEMM_SMEM>>>(
        sh + HF_SS, sh + HF_WTATT, sh + HF_ATTR, 512, 512, 512, 512, 0, 0, 0, 1.f);
    ln512w_kernel<<<2048, 256>>>(sh + HF_ATTR, sh + HF_ATT, g_att, b_att);

    // -- side stream: h1 = ss @ W_hidden --
    cudaStreamWaitEvent(s1, eS, 0);
    gemm_h_kernel<<<dim3(4, 128, 1), 256, GEMM_SMEM, s1>>>(
        sh + HF_SS, sh + HF_WTHID, sh + HF_H1, 512, 512, 512, 512, 0, 0, 0, 1.f);
    cudaEventRecord(eH, s1);

    // -- main: attention chain (align scores pre-scaled by 1/sqrt(D)) --
    cudaStreamWaitEvent(0, eP, 0);
    gemm_h_kernel<<<dim3(4, 4, 32), 256, GEMM_SMEM>>>(
        sh + HF_ATT, sh + HF_PCTX, sh + HF_SC, 512,
        bDS, 512, 512, kD, (long)kS * kD, (long)kT * kS, invsq);
    softmaxw_kernel<<<2048, 256>>>(sh + HF_SC, sh + HF_AV, out_pattn, mlen);
    gemm_h_kernel<<<dim3(4, 4, 32), 256, GEMM_SMEM>>>(
        sh + HF_AV, sh + HF_PCTXT, sh + HF_AO, 512,
        512, 512, bDS, (long)kT * kS, (long)kD * kS, kD, invsq);
    gemm_h_kernel<<<dim3(4, 128, 1), 256, GEMM_SMEM>>>(
        sh + HF_AO, sh + HF_WTCTX, sh + HF_H2, 512, 512, 512, 512, 0, 0, 0, 1.f);

    // join h1, final blend
    cudaStreamWaitEvent(0, eH, 0);
    finalw_kernel<<<2048, 256>>>(sh + HF_H1, sh + HF_H2, sh + HF_HG, prev,
                                 g_h, b_h, g_c, b_c, out);
    cudaMemcpyAsync(out_hid, sf, (size_t)kB * kD * sizeof(float),
                    cudaMemcpyDeviceToDevice, 0);
    // (stream/events intentionally leaked: destroying mid-capture invalidates it)
}

// round 13
// speedup vs baseline: 1.3246x; 1.3246x over previous
#include <cuda_runtime.h>
#include <cuda_fp16.h>
#include <math.h>
#include <stdint.h>

// ---------------------------------------------------------------------------
// AttSRU: T=512, B=32, S=512, D=512, fp32 I/O.
// Round 13: R11 structure (block-per-row elementwise, fp16 mma GEMMs, fp16
// intermediates) + fused multi-value block reductions (half the barriers)
// + 1/sqrt(D) folded into align GEMM alpha.
// ---------------------------------------------------------------------------

namespace {
constexpr int  kT = 512, kB = 32, kS = 512, kD = 512;
constexpr long kTB   = (long)kT * kB;      // 16384 rows
constexpr long kTBD  = kTB * kD;           // 8388608
constexpr float kEPS = 1e-6f;

// fp16 scratch offsets (halfs)
constexpr long HF_PREV  = 0;
constexpr long HF_ENC   = HF_PREV  + kTBD;
constexpr long HF_PCTXR = HF_ENC   + kTBD;
constexpr long HF_PCTX  = HF_PCTXR + kTBD;
constexpr long HF_PCTXT = HF_PCTX  + kTBD;
constexpr long HF_SS    = HF_PCTXT + kTBD;
constexpr long HF_ATTR  = HF_SS    + kTBD;
constexpr long HF_ATT   = HF_ATTR  + kTBD;
constexpr long HF_SC    = HF_ATT   + kTBD;   // align scores (pre-scaled)
constexpr long HF_AV    = HF_SC    + kTBD;
constexpr long HF_AO    = HF_AV    + kTBD;
constexpr long HF_H1    = HF_AO    + kTBD;
constexpr long HF_H2    = HF_H1    + kTBD;
constexpr long HF_Z     = HF_H2    + kTBD;
constexpr long HF_HG    = HF_Z     + kTBD;
constexpr long HF_PL    = HF_HG    + kTBD;
constexpr long HF_PRE   = HF_PL    + kTBD;   // [TB,3D]
constexpr long HF_WTIN  = HF_PRE   + 3 * kTBD;
constexpr long HF_WTENC = HF_WTIN  + (long)3 * kD * kD;
constexpr long HF_WTATT = HF_WTENC + (long)kD * kD;
constexpr long HF_WTHID = HF_WTATT + (long)kD * kD;
constexpr long HF_WTCTX = HF_WTHID + (long)kD * kD;
constexpr long kSCH     = HF_WTCTX + (long)kD * kD;

constexpr long kSCF = (long)kB * kD;          // final scan state (fp32)

// fp16 GEMM smem: K-chunk 32 halfs/row, row stride 40 halfs (80B)
constexpr int RSH = 40;
constexpr int OPH = 128 * RSH;
constexpr int STG = 2 * OPH;
constexpr int GEMM_SMEM = 3 * STG * 2;        // 61440 B -> 2 CTAs/SM
}

__device__ float  g_scf[kSCF];
__device__ __half g_sch[kSCH];

// ---------------------------------------------------------------------------
// Helpers
// ---------------------------------------------------------------------------
__device__ __forceinline__ float warpSum(float v) {
#pragma unroll
    for (int o = 16; o; o >>= 1) v += __shfl_xor_sync(0xffffffffu, v, o);
    return v;
}
__device__ __forceinline__ float warpMax(float v) {
#pragma unroll
    for (int o = 16; o; o >>= 1) v = fmaxf(v, __shfl_xor_sync(0xffffffffu, v, o));
    return v;
}
// fused 2-value block sum (one barrier pair instead of two)
__device__ __forceinline__ float2 blockSum2(float a, float b, float2* sh) {
    int w = threadIdx.x >> 5, l = threadIdx.x & 31, nw = blockDim.x >> 5;
    a = warpSum(a);
    b = warpSum(b);
    if (l == 0) sh[w] = make_float2(a, b);
    __syncthreads();
    float2 v = (l < nw) ? sh[l] : make_float2(0.f, 0.f);
    v.x = warpSum(v.x);
    v.y = warpSum(v.y);
    return v;      // no trailing barrier: smem not reused afterwards
}
// fused 4-value block sum
__device__ __forceinline__ float4 blockSum4(float a, float b, float c, float d,
                                            float4* sh) {
    int w = threadIdx.x >> 5, l = threadIdx.x & 31, nw = blockDim.x >> 5;
    a = warpSum(a); b = warpSum(b); c = warpSum(c); d = warpSum(d);
    if (l == 0) sh[w] = make_float4(a, b, c, d);
    __syncthreads();
    float4 v = (l < nw) ? sh[l] : make_float4(0.f, 0.f, 0.f, 0.f);
    v.x = warpSum(v.x); v.y = warpSum(v.y);
    v.z = warpSum(v.z); v.w = warpSum(v.w);
    return v;
}
__device__ __forceinline__ float blockMax(float v, float* sh) {
    int w = threadIdx.x >> 5, l = threadIdx.x & 31, nw = blockDim.x >> 5;
    v = warpMax(v);
    if (l == 0) sh[w] = v;
    __syncthreads();
    v = (l < nw) ? sh[l] : -INFINITY;
    v = warpMax(v);
    __syncthreads();
    return v;
}
__device__ __forceinline__ float blockSumS(float v, float* sh) {
    int w = threadIdx.x >> 5, l = threadIdx.x & 31, nw = blockDim.x >> 5;
    v = warpSum(v);
    if (l == 0) sh[w] = v;
    __syncthreads();
    v = (l < nw) ? sh[l] : 0.f;
    v = warpSum(v);
    return v;
}
__device__ __forceinline__ float sigm(float x) { return 1.f / (1.f + expf(-x)); }

// load 4 consecutive halfs -> 4 floats
__device__ __forceinline__ void ld4h(const __half* p, float& a, float& b,
                                     float& c, float& d) {
    uint2 r = *reinterpret_cast<const uint2*>(p);
    __half2 h0 = *reinterpret_cast<__half2*>(&r.x);
    __half2 h1 = *reinterpret_cast<__half2*>(&r.y);
    float2 f0 = __half22float2(h0), f1 = __half22float2(h1);
    a = f0.x; b = f0.y; c = f1.x; d = f1.y;
}
// store 4 floats -> 4 consecutive halfs
__device__ __forceinline__ void st4h(__half* p, float a, float b, float c, float d) {
    uint2 r;
    __half2 h0 = __floats2half2_rn(a, b), h1 = __floats2half2_rn(c, d);
    r.x = *reinterpret_cast<uint32_t*>(&h0);
    r.y = *reinterpret_cast<uint32_t*>(&h1);
    *reinterpret_cast<uint2*>(p) = r;
}

__device__ __forceinline__ void ldsm4(uint32_t& r0, uint32_t& r1,
                                      uint32_t& r2, uint32_t& r3, uint32_t addr) {
    asm volatile("ldmatrix.sync.aligned.m8n8.x4.shared.b16 {%0,%1,%2,%3}, [%4];"
                 : "=r"(r0), "=r"(r1), "=r"(r2), "=r"(r3) : "r"(addr));
}

// ---------------------------------------------------------------------------
// fp16 mma GEMM: C[M,N] = alpha * A[M,K] @ B[N,K]^T  (fp32 accum, fp16 out)
// Grid: (N/128, M/128, batch). Block: 256 (8 warps 4x2, warp tile 32x64).
// ---------------------------------------------------------------------------
__global__ __launch_bounds__(256, 2)
void gemm_h_kernel(const __half* __restrict__ A, const __half* __restrict__ B,
                   __half* __restrict__ C, int K,
                   long lda, long ldb, long ldc,
                   long sA, long sB, long sC, float alpha)
{
    extern __shared__ __half smh[];
    const uint32_t sb = (uint32_t)__cvta_generic_to_shared(smh);
    A += (long)blockIdx.z * sA;
    B += (long)blockIdx.z * sB;
    C += (long)blockIdx.z * sC;
    const int bm = blockIdx.y * 128, bn = blockIdx.x * 128;
    const int tid = threadIdx.x, wid = tid >> 5, lane = tid & 31;
    const int mw = (wid >> 1) * 32, nw = (wid & 1) * 64;
    const int lr = lane >> 2, lc = lane & 3;

    const int aoff = (mw + (lane & 15)) * RSH + (lane >> 4) * 8;
    const int boff0 = OPH + (nw + (lane & 7) + (lane >> 4) * 8) * RSH
                    + ((lane >> 3) & 1) * 8;

    const __half* gp[4];
    uint32_t dsto[4];
#pragma unroll
    for (int i = 0; i < 4; i++) {
        int id = tid + i * 256;
        bool isA = id < 512;
        int rid = id & 511;
        int row = rid >> 2, q = rid & 3;
        gp[i] = (isA ? A + (long)(bm + row) * lda
                     : B + (long)(bn + row) * ldb) + q * 8;
        dsto[i] = (isA ? 0u : (uint32_t)OPH) + (uint32_t)(row * RSH + q * 8);
    }
    const int nch = K >> 5;

    auto load_chunk = [&](int c, int s) {
        long ko = (long)c * 32;
        uint32_t base = (uint32_t)(s * STG);
#pragma unroll
        for (int i = 0; i < 4; i++) {
            uint32_t d = sb + (base + dsto[i]) * 2u;
            asm volatile("cp.async.cg.shared.global [%0], [%1], 16;"
                         :: "r"(d), "l"(gp[i] + ko));
        }
    };

    float acc[2][8][4];
#pragma unroll
    for (int i = 0; i < 2; i++)
#pragma unroll
        for (int j = 0; j < 8; j++)
#pragma unroll
            for (int v = 0; v < 4; v++) acc[i][j][v] = 0.f;

    load_chunk(0, 0);
    asm volatile("cp.async.commit_group;");
    if (nch > 1) {
        load_chunk(1, 1);
        asm volatile("cp.async.commit_group;");
    }

    for (int c = 0; c < nch; c++) {
        if (c + 1 < nch) asm volatile("cp.async.wait_group 1;");
        else             asm volatile("cp.async.wait_group 0;");
        __syncthreads();
        if (c + 2 < nch) {
            load_chunk(c + 2, (c + 2) % 3);
            asm volatile("cp.async.commit_group;");
        }
        const uint32_t stb = sb + (uint32_t)((c % 3) * STG) * 2u;
#pragma unroll
        for (int ks = 0; ks < 2; ks++) {
            const uint32_t kb = (uint32_t)(ks * 16) * 2u;
            uint32_t a[2][4];
#pragma unroll
            for (int im = 0; im < 2; im++)
                ldsm4(a[im][0], a[im][1], a[im][2], a[im][3],
                      stb + (uint32_t)(aoff + im * 16 * RSH) * 2u + kb);
#pragma unroll
            for (int p = 0; p < 4; p++) {
                uint32_t b0, b1, b2, b3;
                ldsm4(b0, b1, b2, b3, stb + (uint32_t)(boff0 + p * 16 * RSH) * 2u + kb);
#pragma unroll
                for (int im = 0; im < 2; im++) {
                    asm volatile(
                        "mma.sync.aligned.m16n8k16.row.col.f32.f16.f16.f32 "
                        "{%0,%1,%2,%3}, {%4,%5,%6,%7}, {%8,%9}, {%0,%1,%2,%3};"
                        : "+f"(acc[im][2 * p][0]), "+f"(acc[im][2 * p][1]),
                          "+f"(acc[im][2 * p][2]), "+f"(acc[im][2 * p][3])
                        : "r"(a[im][0]), "r"(a[im][1]), "r"(a[im][2]), "r"(a[im][3]),
                          "r"(b0), "r"(b1));
                    asm volatile(
                        "mma.sync.aligned.m16n8k16.row.col.f32.f16.f16.f32 "
                        "{%0,%1,%2,%3}, {%4,%5,%6,%7}, {%8,%9}, {%0,%1,%2,%3};"
                        : "+f"(acc[im][2 * p + 1][0]), "+f"(acc[im][2 * p + 1][1]),
                          "+f"(acc[im][2 * p + 1][2]), "+f"(acc[im][2 * p + 1][3])
                        : "r"(a[im][0]), "r"(a[im][1]), "r"(a[im][2]), "r"(a[im][3]),
                          "r"(b2), "r"(b3));
                }
            }
        }
    }

#pragma unroll
    for (int im = 0; im < 2; im++) {
        long r0 = (long)(bm + mw + im * 16 + lr);
#pragma unroll
        for (int jn = 0; jn < 8; jn++) {
            long col = bn + nw + jn * 8 + lc * 2;
            *reinterpret_cast<__half2*>(C + r0 * ldc + col) =
                __floats2half2_rn(acc[im][jn][0] * alpha, acc[im][jn][1] * alpha);
            *reinterpret_cast<__half2*>(C + (r0 + 8) * ldc + col) =
                __floats2half2_rn(acc[im][jn][2] * alpha, acc[im][jn][3] * alpha);
        }
    }
}

// ---------------------------------------------------------------------------
// fp32 -> fp16 convert
// ---------------------------------------------------------------------------
__global__ void f2h_kernel(const float* __restrict__ in, __half* __restrict__ out,
                           long n4)
{
    long i = (long)blockIdx.x * blockDim.x + threadIdx.x;
    if (i >= n4) return;
    float4 v = reinterpret_cast<const float4*>(in)[i];
    reinterpret_cast<__half2*>(out)[i * 2]     = __floats2half2_rn(v.x, v.y);
    reinterpret_cast<__half2*>(out)[i * 2 + 1] = __floats2half2_rn(v.z, v.w);
}

// ---------------------------------------------------------------------------
// Transposes
// ---------------------------------------------------------------------------
__global__ void transpose_f2h_kernel(const float* __restrict__ in,
                                     __half* __restrict__ out,
                                     int R, int C, long sIn, long sOut)
{
    __shared__ float t[32][33];
    in  += (long)blockIdx.z * sIn;
    out += (long)blockIdx.z * sOut;
    int bx = blockIdx.x * 32, by = blockIdx.y * 32;
    int x = threadIdx.x, y = threadIdx.y;
#pragma unroll
    for (int i = 0; i < 32; i += 8) t[y + i][x] = in[(long)(by + y + i) * C + bx + x];
    __syncthreads();
#pragma unroll
    for (int i = 0; i < 32; i += 8)
        out[(long)(bx + y + i) * R + by + x] = __float2half_rn(t[x][y + i]);
}

__global__ void transpose4_f2h_kernel(const float* __restrict__ w0, const float* __restrict__ w1,
                                      const float* __restrict__ w2, const float* __restrict__ w3,
                                      __half* __restrict__ o0, __half* __restrict__ o1,
                                      __half* __restrict__ o2, __half* __restrict__ o3)
{
    __shared__ float t[32][33];
    const float* in; __half* out;
    switch (blockIdx.z) {
        case 0: in = w0; out = o0; break;
        case 1: in = w1; out = o1; break;
        case 2: in = w2; out = o2; break;
        default: in = w3; out = o3; break;
    }
    int bx = blockIdx.x * 32, by = blockIdx.y * 32;
    int x = threadIdx.x, y = threadIdx.y;
#pragma unroll
    for (int i = 0; i < 32; i += 8) t[y + i][x] = in[(long)(by + y + i) * kD + bx + x];
    __syncthreads();
#pragma unroll
    for (int i = 0; i < 32; i += 8)
        out[(long)(bx + y + i) * kD + by + x] = __float2half_rn(t[x][y + i]);
}

__global__ void transpose_h2h_kernel(const __half* __restrict__ in,
                                     __half* __restrict__ out,
                                     int R, int C, long sIn, long sOut)
{
    __shared__ __half t[32][34];
    in  += (long)blockIdx.z * sIn;
    out += (long)blockIdx.z * sOut;
    int bx = blockIdx.x * 32, by = blockIdx.y * 32;
    int x = threadIdx.x, y = threadIdx.y;
#pragma unroll
    for (int i = 0; i < 32; i += 8) t[y + i][x] = in[(long)(by + y + i) * C + bx + x];
    __syncthreads();
#pragma unroll
    for (int i = 0; i < 32; i += 8)
        out[(long)(bx + y + i) * R + by + x] = t[x][y + i];
}

// ---------------------------------------------------------------------------
// LN over 3D=1536 (fp16 in), split + sigmoid -> fp16 Z / HG / PL. block=384.
// ---------------------------------------------------------------------------
__global__ void ln_preact_kernel(const __half* __restrict__ pre,
                                 const float* __restrict__ g, const float* __restrict__ bb,
                                 __half* __restrict__ Z, __half* __restrict__ HG,
                                 __half* __restrict__ PL)
{
    __shared__ float2 sh[32];
    long row = blockIdx.x;
    int c = threadIdx.x * 4;
    float vx, vy, vz, vw;
    ld4h(pre + row * (3 * kD) + c, vx, vy, vz, vw);
    float s = vx + vy + vz + vw;
    float q = vx * vx + vy * vy + vz * vz + vw * vw;
    float2 sq = blockSum2(s, q, sh);
    const float invW = 1.f / (3 * kD);
    float m  = sq.x * invW;
    float rv = rsqrtf(sq.y * invW - m * m + kEPS);
    float n0 = g[c + 0] * ((vx - m) * rv) + bb[c + 0];
    float n1 = g[c + 1] * ((vy - m) * rv) + bb[c + 1];
    float n2 = g[c + 2] * ((vz - m) * rv) + bb[c + 2];
    float n3 = g[c + 3] * ((vw - m) * rv) + bb[c + 3];
    long rD = row * kD;
    if (c < kD) {
        st4h(Z + rD + c, sigm(n0), sigm(n1), sigm(n2), sigm(n3));
    } else if (c < 2 * kD) {
        st4h(HG + rD + (c - kD), sigm(n0), sigm(n1), sigm(n2), sigm(n3));
    } else {
        st4h(PL + rD + (c - 2 * kD), n0, n1, n2, n3);
    }
}

// LN over D=512: fp16 in -> fp16 out. block=128, grid=rows.
__global__ void ln512h_kernel(const __half* __restrict__ x, __half* __restrict__ out,
                              const float* __restrict__ g, const float* __restrict__ b)
{
    __shared__ float2 sh[32];
    long row = blockIdx.x;
    int c = threadIdx.x * 4;
    float vx, vy, vz, vw;
    ld4h(x + row * kD + c, vx, vy, vz, vw);
    float s = vx + vy + vz + vw;
    float q = vx * vx + vy * vy + vz * vz + vw * vw;
    float2 sq = blockSum2(s, q, sh);
    const float invW = 1.f / kD;
    float m  = sq.x * invW;
    float rv = rsqrtf(sq.y * invW - m * m + kEPS);
    st4h(out + row * kD + c,
         g[c + 0] * ((vx - m) * rv) + b[c + 0],
         g[c + 1] * ((vy - m) * rv) + b[c + 1],
         g[c + 2] * ((vz - m) * rv) + b[c + 2],
         g[c + 3] * ((vw - m) * rv) + b[c + 3]);
}

// SRU scan over half2 lanes: fp32 state, fp16 ss out, fp32 final state.
__global__ __launch_bounds__(64)
void scan_kernel(const __half2* __restrict__ Z, const __half2* __restrict__ PL,
                 const float* __restrict__ h0, __half2* __restrict__ ssh,
                 float* __restrict__ sslast)
{
    constexpr int BATCH = 16;
    int idx = blockIdx.x * 64 + threadIdx.x;
    float2 s = reinterpret_cast<const float2*>(h0)[idx];
    const long stride = (long)kB * kD / 2;
    long off = idx;
    for (int g = 0; g < kT / BATCH; g++) {
        __half2 z[BATCH], p[BATCH];
#pragma unroll
        for (int j = 0; j < BATCH; j++) z[j] = Z[off + j * stride];
#pragma unroll
        for (int j = 0; j < BATCH; j++) p[j] = PL[off + j * stride];
#pragma unroll
        for (int j = 0; j < BATCH; j++) {
            float2 zf = __half22float2(z[j]);
            float2 pf = __half22float2(p[j]);
            s.x = (1.f - zf.x) * s.x + zf.x * pf.x;
            s.y = (1.f - zf.y) * s.y + zf.y * pf.y;
            ssh[off + j * stride] = __floats2half2_rn(s.x, s.y);
        }
        off += (long)BATCH * stride;
    }
    reinterpret_cast<float2*>(sslast)[idx] = s;
}

// Masked softmax over S=512: fp16 pre-scaled scores in; fp32 p_attn + fp16 probs.
__global__ void softmax_kernel(const __half* __restrict__ sc, __half* __restrict__ avh,
                               float* __restrict__ pattn, const int* __restrict__ mlen)
{
    __shared__ float sh[32];
    long row = blockIdx.x;                 // b*T + t
    int b = (int)(row / kT), t = (int)(row % kT);
    int ml = mlen[b];
    int c = threadIdx.x * 4;
    float x0, x1, x2, x3;
    ld4h(sc + row * kS + c, x0, x1, x2, x3);
    float mx = -INFINITY;
    if (c + 0 < ml) mx = fmaxf(mx, x0);
    if (c + 1 < ml) mx = fmaxf(mx, x1);
    if (c + 2 < ml) mx = fmaxf(mx, x2);
    if (c + 3 < ml) mx = fmaxf(mx, x3);
    mx = blockMax(mx, sh);
    float e0 = (c + 0 < ml) ? expf(x0 - mx) : 0.f;
    float e1 = (c + 1 < ml) ? expf(x1 - mx) : 0.f;
    float e2 = (c + 2 < ml) ? expf(x2 - mx) : 0.f;
    float e3 = (c + 3 < ml) ? expf(x3 - mx) : 0.f;
    float sum = blockSumS(e0 + e1 + e2 + e3, sh);
    float is = 1.f / sum;
    float4 o = make_float4(e0 * is, e1 * is, e2 * is, e3 * is);
    *reinterpret_cast<float4*>(pattn + ((long)t * kB + b) * kS + c) = o;
    st4h(avh + row * kS + c, o.x, o.y, o.z, o.w);
}

// out = (1-hg)*tanh(LN(h1)+LN(h2)) + hg*prev   (h1,h2,HG fp16; prev,out fp32)
__global__ void final_kernel(const __half* __restrict__ h1, const __half* __restrict__ h2,
                             const __half* __restrict__ HG, const float* __restrict__ prev,
                             const float* __restrict__ g_h, const float* __restrict__ b_h,
                             const float* __restrict__ g_c, const float* __restrict__ b_c,
                             float* __restrict__ out)
{
    __shared__ float4 sh[32];
    long row = blockIdx.x;
    int c = threadIdx.x * 4;
    float ax, ay, az, aw, dx, dy, dz, dw;
    ld4h(h1 + row * kD + c, ax, ay, az, aw);
    ld4h(h2 + row * kD + c, dx, dy, dz, dw);
    float s1 = ax + ay + az + aw;
    float q1 = ax * ax + ay * ay + az * az + aw * aw;
    float s2 = dx + dy + dz + dw;
    float q2 = dx * dx + dy * dy + dz * dz + dw * dw;
    float4 r4 = blockSum4(s1, q1, s2, q2, sh);
    const float invW = 1.f / kD;
    float m1 = r4.x * invW, r1 = rsqrtf(r4.y * invW - m1 * m1 + kEPS);
    float m2 = r4.z * invW, r2 = rsqrtf(r4.w * invW - m2 * m2 + kEPS);
    float h0, h1v, h2v, h3;
    ld4h(HG + row * kD + c, h0, h1v, h2v, h3);
    float4 pv = *reinterpret_cast<const float4*>(prev + row * kD + c);
    float t0 = tanhf(g_h[c + 0] * ((ax - m1) * r1) + b_h[c + 0] +
                     g_c[c + 0] * ((dx - m2) * r2) + b_c[c + 0]);
    float t1 = tanhf(g_h[c + 1] * ((ay - m1) * r1) + b_h[c + 1] +
                     g_c[c + 1] * ((dy - m2) * r2) + b_c[c + 1]);
    float t2 = tanhf(g_h[c + 2] * ((az - m1) * r1) + b_h[c + 2] +
                     g_c[c + 2] * ((dz - m2) * r2) + b_c[c + 2]);
    float t3 = tanhf(g_h[c + 3] * ((aw - m1) * r1) + b_h[c + 3] +
                     g_c[c + 3] * ((dw - m2) * r2) + b_c[c + 3]);
    float4 o;
    o.x = (1.f - h0)  * t0 + h0  * pv.x;
    o.y = (1.f - h1v) * t1 + h1v * pv.y;
    o.z = (1.f - h2v) * t2 + h2v * pv.z;
    o.w = (1.f - h3)  * t3 + h3  * pv.w;
    *reinterpret_cast<float4*>(out + row * kD + c) = o;
}

// ---------------------------------------------------------------------------
// Launch
// ---------------------------------------------------------------------------
extern "C" void kernel_launch(void* const* d_in, const int* in_sizes, int n_in,
                              void* d_out, int out_size)
{
    int i_prev = -1, i_enc = -1, i_hidden = -1, i_ml = -1, i_Win = -1;
    int w4[4] = {-1, -1, -1, -1}; int n4 = 0;
    int p2[2] = {-1, -1};         int np = 0;
    int v8[8] = {-1, -1, -1, -1, -1, -1, -1, -1}; int nv = 0;
    for (int i = 0; i < n_in; i++) {
        switch (in_sizes[i]) {
            case 8388608: if (i_prev < 0) i_prev = i; else i_enc = i; break;
            case 16384:   i_hidden = i; break;
            case 32:      i_ml = i; break;
            case 786432:  i_Win = i; break;
            case 262144:  if (n4 < 4) w4[n4++] = i; break;
            case 1536:    if (np < 2) p2[np++] = i; break;
            case 512:     if (nv < 8) v8[nv++] = i; break;
            default: break;
        }
    }
    const float* prev   = (const float*)d_in[i_prev];
    const float* hidden = (const float*)d_in[i_hidden];
    const float* enc    = (const float*)d_in[i_enc];
    const int*   mlen   = (const int*)d_in[i_ml];
    const float* W_in   = (const float*)d_in[i_Win];
    const float* W_enc  = (const float*)d_in[w4[0]];
    const float* W_att  = (const float*)d_in[w4[1]];
    const float* W_hid  = (const float*)d_in[w4[2]];
    const float* W_ctx  = (const float*)d_in[w4[3]];
    const float* g_pre  = (const float*)d_in[p2[0]];
    const float* b_pre  = (const float*)d_in[p2[1]];
    const float* g_enc  = (const float*)d_in[v8[0]];
    const float* b_enc  = (const float*)d_in[v8[1]];
    const float* g_att  = (const float*)d_in[v8[2]];
    const float* b_att  = (const float*)d_in[v8[3]];
    const float* g_h    = (const float*)d_in[v8[4]];
    const float* b_h    = (const float*)d_in[v8[5]];
    const float* g_c    = (const float*)d_in[v8[6]];
    const float* b_c    = (const float*)d_in[v8[7]];

    float* sf = nullptr;
    __half* sh = nullptr;
    cudaGetSymbolAddress((void**)&sf, g_scf);
    cudaGetSymbolAddress((void**)&sh, g_sch);

    float* out       = (float*)d_out;            // [T,B,D]
    float* out_hid   = out + kTBD;               // [B,D]
    float* out_pattn = out_hid + (long)kB * kD;  // [T,B,S]

    cudaFuncSetAttribute(gemm_h_kernel,
                         cudaFuncAttributeMaxDynamicSharedMemorySize, GEMM_SMEM);

    dim3 tb(32, 8);
    const float invsq = rsqrtf((float)kD);
    const long bDS = (long)kB * kD;

    cudaStream_t s1;
    cudaStreamCreateWithFlags(&s1, cudaStreamNonBlocking);
    cudaEvent_t eW, eP, eS, eH;
    cudaEventCreateWithFlags(&eW, cudaEventDisableTiming);
    cudaEventCreateWithFlags(&eP, cudaEventDisableTiming);
    cudaEventCreateWithFlags(&eS, cudaEventDisableTiming);
    cudaEventCreateWithFlags(&eH, cudaEventDisableTiming);

    // -- side stream: enc convert --
    f2h_kernel<<<8192, 256, 0, s1>>>(enc, sh + HF_ENC, kTBD / 4);

    // -- main: prev convert + weight transposes --
    f2h_kernel<<<8192, 256>>>(prev, sh + HF_PREV, kTBD / 4);
    transpose_f2h_kernel<<<dim3(16, 16, 3), tb>>>(W_in, sh + HF_WTIN, kD, 3 * kD,
                                                  512, (long)kD * kD);
    transpose4_f2h_kernel<<<dim3(16, 16, 4), tb>>>(W_enc, W_att, W_hid, W_ctx,
                                                   sh + HF_WTENC, sh + HF_WTATT,
                                                   sh + HF_WTHID, sh + HF_WTCTX);
    cudaEventRecord(eW, 0);

    // -- side stream: enc chain --
    cudaStreamWaitEvent(s1, eW, 0);
    gemm_h_kernel<<<dim3(4, 128, 1), 256, GEMM_SMEM, s1>>>(
        sh + HF_ENC, sh + HF_WTENC, sh + HF_PCTXR, 512, 512, 512, 512, 0, 0, 0, 1.f);
    ln512h_kernel<<<(unsigned)kTB, 128, 0, s1>>>(sh + HF_PCTXR, sh + HF_PCTX,
                                                 g_enc, b_enc);
    transpose_h2h_kernel<<<dim3(16, 16, 32), tb, 0, s1>>>(
        sh + HF_PCTX, sh + HF_PCTXT, kS, kD, (long)kS * kD, (long)kD * kS);
    cudaEventRecord(eP, s1);

    // -- main: preact chain --
    gemm_h_kernel<<<dim3(12, 128, 1), 256, GEMM_SMEM>>>(
        sh + HF_PREV, sh + HF_WTIN, sh + HF_PRE, 512, 512, 512, 1536, 0, 0, 0, 1.f);
    ln_preact_kernel<<<(unsigned)kTB, 384>>>(sh + HF_PRE, g_pre, b_pre,
                                             sh + HF_Z, sh + HF_HG, sh + HF_PL);
    scan_kernel<<<128, 64>>>(reinterpret_cast<__half2*>(sh + HF_Z),
                             reinterpret_cast<__half2*>(sh + HF_PL), hidden,
                             reinterpret_cast<__half2*>(sh + HF_SS), sf);
    cudaEventRecord(eS, 0);
    gemm_h_kernel<<<dim3(4, 128, 1), 256, GEMM_SMEM>>>(
        sh + HF_SS, sh + HF_WTATT, sh + HF_ATTR, 512, 512, 512, 512, 0, 0, 0, 1.f);
    ln512h_kernel<<<(unsigned)kTB, 128>>>(sh + HF_ATTR, sh + HF_ATT, g_att, b_att);

    // -- side stream: h1 = ss @ W_hidden --
    cudaStreamWaitEvent(s1, eS, 0);
    gemm_h_kernel<<<dim3(4, 128, 1), 256, GEMM_SMEM, s1>>>(
        sh + HF_SS, sh + HF_WTHID, sh + HF_H1, 512, 512, 512, 512, 0, 0, 0, 1.f);
    cudaEventRecord(eH, s1);

    // -- main: attention chain (align scores pre-scaled by 1/sqrt(D)) --
    cudaStreamWaitEvent(0, eP, 0);
    gemm_h_kernel<<<dim3(4, 4, 32), 256, GEMM_SMEM>>>(
        sh + HF_ATT, sh + HF_PCTX, sh + HF_SC, 512,
        bDS, 512, 512, kD, (long)kS * kD, (long)kT * kS, invsq);
    softmax_kernel<<<(unsigned)(kB * kT), 128>>>(sh + HF_SC, sh + HF_AV,
                                                 out_pattn, mlen);
    gemm_h_kernel<<<dim3(4, 4, 32), 256, GEMM_SMEM>>>(
        sh + HF_AV, sh + HF_PCTXT, sh + HF_AO, 512,
        512, 512, bDS, (long)kT * kS, (long)kD * kS, kD, invsq);
    gemm_h_kernel<<<dim3(4, 128, 1), 256, GEMM_SMEM>>>(
        sh + HF_AO, sh + HF_WTCTX, sh + HF_H2, 512, 512, 512, 512, 0, 0, 0, 1.f);

    // join h1, final blend
    cudaStreamWaitEvent(0, eH, 0);
    final_kernel<<<(unsigned)kTB, 128>>>(sh + HF_H1, sh + HF_H2, sh + HF_HG, prev,
                                         g_h, b_h, g_c, b_c, out);
    cudaMemcpyAsync(out_hid, sf, (size_t)kB * kD * sizeof(float),
                    cudaMemcpyDeviceToDevice, 0);
    // (stream/events intentionally leaked: destroying mid-capture invalidates it)
}

// round 15
// speedup vs baseline: 1.3631x; 1.0291x over previous
#include <cuda_runtime.h>
#include <cuda_fp16.h>
#include <math.h>
#include <stdint.h>

// ---------------------------------------------------------------------------
// AttSRU: T=512, B=32, S=512, D=512, fp32 I/O.
// Round 14: R13 + reassociation h2 = av @ (pctx @ W_ctx) / sqrt(d).
// pcw GEMM runs on the side stream (overlapped); one GEMM removed from the
// post-softmax critical path; AO intermediate eliminated.
// ---------------------------------------------------------------------------

namespace {
constexpr int  kT = 512, kB = 32, kS = 512, kD = 512;
constexpr long kTB   = (long)kT * kB;      // 16384 rows
constexpr long kTBD  = kTB * kD;           // 8388608
constexpr float kEPS = 1e-6f;

// fp16 scratch offsets (halfs)
constexpr long HF_PREV  = 0;
constexpr long HF_ENC   = HF_PREV  + kTBD;
constexpr long HF_PCTXR = HF_ENC   + kTBD;
constexpr long HF_PCTX  = HF_PCTXR + kTBD;
constexpr long HF_PCW   = HF_PCTX  + kTBD;   // pctx @ W_ctx   [B,S,D]
constexpr long HF_PCWT  = HF_PCW   + kTBD;   // transposed     [B,D,S]
constexpr long HF_SS    = HF_PCWT  + kTBD;
constexpr long HF_ATTR  = HF_SS    + kTBD;
constexpr long HF_ATT   = HF_ATTR  + kTBD;
constexpr long HF_SC    = HF_ATT   + kTBD;   // align scores (pre-scaled)
constexpr long HF_AV    = HF_SC    + kTBD;
constexpr long HF_H1    = HF_AV    + kTBD;
constexpr long HF_H2    = HF_H1    + kTBD;
constexpr long HF_Z     = HF_H2    + kTBD;
constexpr long HF_HG    = HF_Z     + kTBD;
constexpr long HF_PL    = HF_HG    + kTBD;
constexpr long HF_PRE   = HF_PL    + kTBD;   // [TB,3D]
constexpr long HF_WTIN  = HF_PRE   + 3 * kTBD;
constexpr long HF_WTENC = HF_WTIN  + (long)3 * kD * kD;
constexpr long HF_WTATT = HF_WTENC + (long)kD * kD;
constexpr long HF_WTHID = HF_WTATT + (long)kD * kD;
constexpr long HF_WTCTX = HF_WTHID + (long)kD * kD;
constexpr long kSCH     = HF_WTCTX + (long)kD * kD;

constexpr long kSCF = (long)kB * kD;          // final scan state (fp32)

// fp16 GEMM smem: K-chunk 32 halfs/row, row stride 40 halfs (80B)
constexpr int RSH = 40;
constexpr int OPH = 128 * RSH;
constexpr int STG = 2 * OPH;
constexpr int GEMM_SMEM = 3 * STG * 2;        // 61440 B -> 2 CTAs/SM
}

__device__ float  g_scf[kSCF];
__device__ __half g_sch[kSCH];

// ---------------------------------------------------------------------------
// Helpers
// ---------------------------------------------------------------------------
__device__ __forceinline__ float warpSum(float v) {
#pragma unroll
    for (int o = 16; o; o >>= 1) v += __shfl_xor_sync(0xffffffffu, v, o);
    return v;
}
__device__ __forceinline__ float warpMax(float v) {
#pragma unroll
    for (int o = 16; o; o >>= 1) v = fmaxf(v, __shfl_xor_sync(0xffffffffu, v, o));
    return v;
}
// fused 2-value block sum (one barrier pair instead of two)
__device__ __forceinline__ float2 blockSum2(float a, float b, float2* sh) {
    int w = threadIdx.x >> 5, l = threadIdx.x & 31, nw = blockDim.x >> 5;
    a = warpSum(a);
    b = warpSum(b);
    if (l == 0) sh[w] = make_float2(a, b);
    __syncthreads();
    float2 v = (l < nw) ? sh[l] : make_float2(0.f, 0.f);
    v.x = warpSum(v.x);
    v.y = warpSum(v.y);
    return v;
}
// fused 4-value block sum
__device__ __forceinline__ float4 blockSum4(float a, float b, float c, float d,
                                            float4* sh) {
    int w = threadIdx.x >> 5, l = threadIdx.x & 31, nw = blockDim.x >> 5;
    a = warpSum(a); b = warpSum(b); c = warpSum(c); d = warpSum(d);
    if (l == 0) sh[w] = make_float4(a, b, c, d);
    __syncthreads();
    float4 v = (l < nw) ? sh[l] : make_float4(0.f, 0.f, 0.f, 0.f);
    v.x = warpSum(v.x); v.y = warpSum(v.y);
    v.z = warpSum(v.z); v.w = warpSum(v.w);
    return v;
}
__device__ __forceinline__ float blockMax(float v, float* sh) {
    int w = threadIdx.x >> 5, l = threadIdx.x & 31, nw = blockDim.x >> 5;
    v = warpMax(v);
    if (l == 0) sh[w] = v;
    __syncthreads();
    v = (l < nw) ? sh[l] : -INFINITY;
    v = warpMax(v);
    __syncthreads();
    return v;
}
__device__ __forceinline__ float blockSumS(float v, float* sh) {
    int w = threadIdx.x >> 5, l = threadIdx.x & 31, nw = blockDim.x >> 5;
    v = warpSum(v);
    if (l == 0) sh[w] = v;
    __syncthreads();
    v = (l < nw) ? sh[l] : 0.f;
    v = warpSum(v);
    return v;
}
__device__ __forceinline__ float sigm(float x) { return 1.f / (1.f + expf(-x)); }

// load 4 consecutive halfs -> 4 floats
__device__ __forceinline__ void ld4h(const __half* p, float& a, float& b,
                                     float& c, float& d) {
    uint2 r = *reinterpret_cast<const uint2*>(p);
    __half2 h0 = *reinterpret_cast<__half2*>(&r.x);
    __half2 h1 = *reinterpret_cast<__half2*>(&r.y);
    float2 f0 = __half22float2(h0), f1 = __half22float2(h1);
    a = f0.x; b = f0.y; c = f1.x; d = f1.y;
}
// store 4 floats -> 4 consecutive halfs
__device__ __forceinline__ void st4h(__half* p, float a, float b, float c, float d) {
    uint2 r;
    __half2 h0 = __floats2half2_rn(a, b), h1 = __floats2half2_rn(c, d);
    r.x = *reinterpret_cast<uint32_t*>(&h0);
    r.y = *reinterpret_cast<uint32_t*>(&h1);
    *reinterpret_cast<uint2*>(p) = r;
}

__device__ __forceinline__ void ldsm4(uint32_t& r0, uint32_t& r1,
                                      uint32_t& r2, uint32_t& r3, uint32_t addr) {
    asm volatile("ldmatrix.sync.aligned.m8n8.x4.shared.b16 {%0,%1,%2,%3}, [%4];"
                 : "=r"(r0), "=r"(r1), "=r"(r2), "=r"(r3) : "r"(addr));
}

// ---------------------------------------------------------------------------
// fp16 mma GEMM: C[M,N] = alpha * A[M,K] @ B[N,K]^T  (fp32 accum, fp16 out)
// Grid: (N/128, M/128, batch). Block: 256 (8 warps 4x2, warp tile 32x64).
// ---------------------------------------------------------------------------
__global__ __launch_bounds__(256, 2)
void gemm_h_kernel(const __half* __restrict__ A, const __half* __restrict__ B,
                   __half* __restrict__ C, int K,
                   long lda, long ldb, long ldc,
                   long sA, long sB, long sC, float alpha)
{
    extern __shared__ __half smh[];
    const uint32_t sb = (uint32_t)__cvta_generic_to_shared(smh);
    A += (long)blockIdx.z * sA;
    B += (long)blockIdx.z * sB;
    C += (long)blockIdx.z * sC;
    const int bm = blockIdx.y * 128, bn = blockIdx.x * 128;
    const int tid = threadIdx.x, wid = tid >> 5, lane = tid & 31;
    const int mw = (wid >> 1) * 32, nw = (wid & 1) * 64;
    const int lr = lane >> 2, lc = lane & 3;

    const int aoff = (mw + (lane & 15)) * RSH + (lane >> 4) * 8;
    const int boff0 = OPH + (nw + (lane & 7) + (lane >> 4) * 8) * RSH
                    + ((lane >> 3) & 1) * 8;

    const __half* gp[4];
    uint32_t dsto[4];
#pragma unroll
    for (int i = 0; i < 4; i++) {
        int id = tid + i * 256;
        bool isA = id < 512;
        int rid = id & 511;
        int row = rid >> 2, q = rid & 3;
        gp[i] = (isA ? A + (long)(bm + row) * lda
                     : B + (long)(bn + row) * ldb) + q * 8;
        dsto[i] = (isA ? 0u : (uint32_t)OPH) + (uint32_t)(row * RSH + q * 8);
    }
    const int nch = K >> 5;

    auto load_chunk = [&](int c, int s) {
        long ko = (long)c * 32;
        uint32_t base = (uint32_t)(s * STG);
#pragma unroll
        for (int i = 0; i < 4; i++) {
            uint32_t d = sb + (base + dsto[i]) * 2u;
            asm volatile("cp.async.cg.shared.global [%0], [%1], 16;"
                         :: "r"(d), "l"(gp[i] + ko));
        }
    };

    float acc[2][8][4];
#pragma unroll
    for (int i = 0; i < 2; i++)
#pragma unroll
        for (int j = 0; j < 8; j++)
#pragma unroll
            for (int v = 0; v < 4; v++) acc[i][j][v] = 0.f;

    load_chunk(0, 0);
    asm volatile("cp.async.commit_group;");
    if (nch > 1) {
        load_chunk(1, 1);
        asm volatile("cp.async.commit_group;");
    }

    for (int c = 0; c < nch; c++) {
        if (c + 1 < nch) asm volatile("cp.async.wait_group 1;");
        else             asm volatile("cp.async.wait_group 0;");
        __syncthreads();
        if (c + 2 < nch) {
            load_chunk(c + 2, (c + 2) % 3);
            asm volatile("cp.async.commit_group;");
        }
        const uint32_t stb = sb + (uint32_t)((c % 3) * STG) * 2u;
#pragma unroll
        for (int ks = 0; ks < 2; ks++) {
            const uint32_t kb = (uint32_t)(ks * 16) * 2u;
            uint32_t a[2][4];
#pragma unroll
            for (int im = 0; im < 2; im++)
                ldsm4(a[im][0], a[im][1], a[im][2], a[im][3],
                      stb + (uint32_t)(aoff + im * 16 * RSH) * 2u + kb);
#pragma unroll
            for (int p = 0; p < 4; p++) {
                uint32_t b0, b1, b2, b3;
                ldsm4(b0, b1, b2, b3, stb + (uint32_t)(boff0 + p * 16 * RSH) * 2u + kb);
#pragma unroll
                for (int im = 0; im < 2; im++) {
                    asm volatile(
                        "mma.sync.aligned.m16n8k16.row.col.f32.f16.f16.f32 "
                        "{%0,%1,%2,%3}, {%4,%5,%6,%7}, {%8,%9}, {%0,%1,%2,%3};"
                        : "+f"(acc[im][2 * p][0]), "+f"(acc[im][2 * p][1]),
                          "+f"(acc[im][2 * p][2]), "+f"(acc[im][2 * p][3])
                        : "r"(a[im][0]), "r"(a[im][1]), "r"(a[im][2]), "r"(a[im][3]),
                          "r"(b0), "r"(b1));
                    asm volatile(
                        "mma.sync.aligned.m16n8k16.row.col.f32.f16.f16.f32 "
                        "{%0,%1,%2,%3}, {%4,%5,%6,%7}, {%8,%9}, {%0,%1,%2,%3};"
                        : "+f"(acc[im][2 * p + 1][0]), "+f"(acc[im][2 * p + 1][1]),
                          "+f"(acc[im][2 * p + 1][2]), "+f"(acc[im][2 * p + 1][3])
                        : "r"(a[im][0]), "r"(a[im][1]), "r"(a[im][2]), "r"(a[im][3]),
                          "r"(b2), "r"(b3));
                }
            }
        }
    }

#pragma unroll
    for (int im = 0; im < 2; im++) {
        long r0 = (long)(bm + mw + im * 16 + lr);
#pragma unroll
        for (int jn = 0; jn < 8; jn++) {
            long col = bn + nw + jn * 8 + lc * 2;
            *reinterpret_cast<__half2*>(C + r0 * ldc + col) =
                __floats2half2_rn(acc[im][jn][0] * alpha, acc[im][jn][1] * alpha);
            *reinterpret_cast<__half2*>(C + (r0 + 8) * ldc + col) =
                __floats2half2_rn(acc[im][jn][2] * alpha, acc[im][jn][3] * alpha);
        }
    }
}

// ---------------------------------------------------------------------------
// fp32 -> fp16 convert
// ---------------------------------------------------------------------------
__global__ void f2h_kernel(const float* __restrict__ in, __half* __restrict__ out,
                           long n4)
{
    long i = (long)blockIdx.x * blockDim.x + threadIdx.x;
    if (i >= n4) return;
    float4 v = reinterpret_cast<const float4*>(in)[i];
    reinterpret_cast<__half2*>(out)[i * 2]     = __floats2half2_rn(v.x, v.y);
    reinterpret_cast<__half2*>(out)[i * 2 + 1] = __floats2half2_rn(v.z, v.w);
}

// ---------------------------------------------------------------------------
// Transposes
// ---------------------------------------------------------------------------
__global__ void transpose_f2h_kernel(const float* __restrict__ in,
                                     __half* __restrict__ out,
                                     int R, int C, long sIn, long sOut)
{
    __shared__ float t[32][33];
    in  += (long)blockIdx.z * sIn;
    out += (long)blockIdx.z * sOut;
    int bx = blockIdx.x * 32, by = blockIdx.y * 32;
    int x = threadIdx.x, y = threadIdx.y;
#pragma unroll
    for (int i = 0; i < 32; i += 8) t[y + i][x] = in[(long)(by + y + i) * C + bx + x];
    __syncthreads();
#pragma unroll
    for (int i = 0; i < 32; i += 8)
        out[(long)(bx + y + i) * R + by + x] = __float2half_rn(t[x][y + i]);
}

__global__ void transpose4_f2h_kernel(const float* __restrict__ w0, const float* __restrict__ w1,
                                      const float* __restrict__ w2, const float* __restrict__ w3,
                                      __half* __restrict__ o0, __half* __restrict__ o1,
                                      __half* __restrict__ o2, __half* __restrict__ o3)
{
    __shared__ float t[32][33];
    const float* in; __half* out;
    switch (blockIdx.z) {
        case 0: in = w0; out = o0; break;
        case 1: in = w1; out = o1; break;
        case 2: in = w2; out = o2; break;
        default: in = w3; out = o3; break;
    }
    int bx = blockIdx.x * 32, by = blockIdx.y * 32;
    int x = threadIdx.x, y = threadIdx.y;
#pragma unroll
    for (int i = 0; i < 32; i += 8) t[y + i][x] = in[(long)(by + y + i) * kD + bx + x];
    __syncthreads();
#pragma unroll
    for (int i = 0; i < 32; i += 8)
        out[(long)(bx + y + i) * kD + by + x] = __float2half_rn(t[x][y + i]);
}

__global__ void transpose_h2h_kernel(const __half* __restrict__ in,
                                     __half* __restrict__ out,
                                     int R, int C, long sIn, long sOut)
{
    __shared__ __half t[32][34];
    in  += (long)blockIdx.z * sIn;
    out += (long)blockIdx.z * sOut;
    int bx = blockIdx.x * 32, by = blockIdx.y * 32;
    int x = threadIdx.x, y = threadIdx.y;
#pragma unroll
    for (int i = 0; i < 32; i += 8) t[y + i][x] = in[(long)(by + y + i) * C + bx + x];
    __syncthreads();
#pragma unroll
    for (int i = 0; i < 32; i += 8)
        out[(long)(bx + y + i) * R + by + x] = t[x][y + i];
}

// ---------------------------------------------------------------------------
// LN over 3D=1536 (fp16 in), split + sigmoid -> fp16 Z / HG / PL. block=384.
// ---------------------------------------------------------------------------
__global__ void ln_preact_kernel(const __half* __restrict__ pre,
                                 const float* __restrict__ g, const float* __restrict__ bb,
                                 __half* __restrict__ Z, __half* __restrict__ HG,
                                 __half* __restrict__ PL)
{
    __shared__ float2 sh[32];
    long row = blockIdx.x;
    int c = threadIdx.x * 4;
    float vx, vy, vz, vw;
    ld4h(pre + row * (3 * kD) + c, vx, vy, vz, vw);
    float s = vx + vy + vz + vw;
    float q = vx * vx + vy * vy + vz * vz + vw * vw;
    float2 sq = blockSum2(s, q, sh);
    const float invW = 1.f / (3 * kD);
    float m  = sq.x * invW;
    float rv = rsqrtf(sq.y * invW - m * m + kEPS);
    float n0 = g[c + 0] * ((vx - m) * rv) + bb[c + 0];
    float n1 = g[c + 1] * ((vy - m) * rv) + bb[c + 1];
    float n2 = g[c + 2] * ((vz - m) * rv) + bb[c + 2];
    float n3 = g[c + 3] * ((vw - m) * rv) + bb[c + 3];
    long rD = row * kD;
    if (c < kD) {
        st4h(Z + rD + c, sigm(n0), sigm(n1), sigm(n2), sigm(n3));
    } else if (c < 2 * kD) {
        st4h(HG + rD + (c - kD), sigm(n0), sigm(n1), sigm(n2), sigm(n3));
    } else {
        st4h(PL + rD + (c - 2 * kD), n0, n1, n2, n3);
    }
}

// LN over D=512: fp16 in -> fp16 out. block=128, grid=rows.
__global__ void ln512h_kernel(const __half* __restrict__ x, __half* __restrict__ out,
                              const float* __restrict__ g, const float* __restrict__ b)
{
    __shared__ float2 sh[32];
    long row = blockIdx.x;
    int c = threadIdx.x * 4;
    float vx, vy, vz, vw;
    ld4h(x + row * kD + c, vx, vy, vz, vw);
    float s = vx + vy + vz + vw;
    float q = vx * vx + vy * vy + vz * vz + vw * vw;
    float2 sq = blockSum2(s, q, sh);
    const float invW = 1.f / kD;
    float m  = sq.x * invW;
    float rv = rsqrtf(sq.y * invW - m * m + kEPS);
    st4h(out + row * kD + c,
         g[c + 0] * ((vx - m) * rv) + b[c + 0],
         g[c + 1] * ((vy - m) * rv) + b[c + 1],
         g[c + 2] * ((vz - m) * rv) + b[c + 2],
         g[c + 3] * ((vw - m) * rv) + b[c + 3]);
}

// SRU scan over half2 lanes: fp32 state, fp16 ss out, fp32 final state.
__global__ __launch_bounds__(64)
void scan_kernel(const __half2* __restrict__ Z, const __half2* __restrict__ PL,
                 const float* __restrict__ h0, __half2* __restrict__ ssh,
                 float* __restrict__ sslast)
{
    constexpr int BATCH = 16;
    int idx = blockIdx.x * 64 + threadIdx.x;
    float2 s = reinterpret_cast<const float2*>(h0)[idx];
    const long stride = (long)kB * kD / 2;
    long off = idx;
    for (int g = 0; g < kT / BATCH; g++) {
        __half2 z[BATCH], p[BATCH];
#pragma unroll
        for (int j = 0; j < BATCH; j++) z[j] = Z[off + j * stride];
#pragma unroll
        for (int j = 0; j < BATCH; j++) p[j] = PL[off + j * stride];
#pragma unroll
        for (int j = 0; j < BATCH; j++) {
            float2 zf = __half22float2(z[j]);
            float2 pf = __half22float2(p[j]);
            s.x = (1.f - zf.x) * s.x + zf.x * pf.x;
            s.y = (1.f - zf.y) * s.y + zf.y * pf.y;
            ssh[off + j * stride] = __floats2half2_rn(s.x, s.y);
        }
        off += (long)BATCH * stride;
    }
    reinterpret_cast<float2*>(sslast)[idx] = s;
}

// Masked softmax over S=512: fp16 pre-scaled scores in; fp32 p_attn + fp16 probs.
__global__ void softmax_kernel(const __half* __restrict__ sc, __half* __restrict__ avh,
                               float* __restrict__ pattn, const int* __restrict__ mlen)
{
    __shared__ float sh[32];
    long row = blockIdx.x;                 // b*T + t
    int b = (int)(row / kT), t = (int)(row % kT);
    int ml = mlen[b];
    int c = threadIdx.x * 4;
    float x0, x1, x2, x3;
    ld4h(sc + row * kS + c, x0, x1, x2, x3);
    float mx = -INFINITY;
    if (c + 0 < ml) mx = fmaxf(mx, x0);
    if (c + 1 < ml) mx = fmaxf(mx, x1);
    if (c + 2 < ml) mx = fmaxf(mx, x2);
    if (c + 3 < ml) mx = fmaxf(mx, x3);
    mx = blockMax(mx, sh);
    float e0 = (c + 0 < ml) ? expf(x0 - mx) : 0.f;
    float e1 = (c + 1 < ml) ? expf(x1 - mx) : 0.f;
    float e2 = (c + 2 < ml) ? expf(x2 - mx) : 0.f;
    float e3 = (c + 3 < ml) ? expf(x3 - mx) : 0.f;
    float sum = blockSumS(e0 + e1 + e2 + e3, sh);
    float is = 1.f / sum;
    float4 o = make_float4(e0 * is, e1 * is, e2 * is, e3 * is);
    *reinterpret_cast<float4*>(pattn + ((long)t * kB + b) * kS + c) = o;
    st4h(avh + row * kS + c, o.x, o.y, o.z, o.w);
}

// out = (1-hg)*tanh(LN(h1)+LN(h2)) + hg*prev   (h1,h2,HG fp16; prev,out fp32)
__global__ void final_kernel(const __half* __restrict__ h1, const __half* __restrict__ h2,
                             const __half* __restrict__ HG, const float* __restrict__ prev,
                             const float* __restrict__ g_h, const float* __restrict__ b_h,
                             const float* __restrict__ g_c, const float* __restrict__ b_c,
                             float* __restrict__ out)
{
    __shared__ float4 sh[32];
    long row = blockIdx.x;
    int c = threadIdx.x * 4;
    float ax, ay, az, aw, dx, dy, dz, dw;
    ld4h(h1 + row * kD + c, ax, ay, az, aw);
    ld4h(h2 + row * kD + c, dx, dy, dz, dw);
    float s1 = ax + ay + az + aw;
    float q1 = ax * ax + ay * ay + az * az + aw * aw;
    float s2 = dx + dy + dz + dw;
    float q2 = dx * dx + dy * dy + dz * dz + dw * dw;
    float4 r4 = blockSum4(s1, q1, s2, q2, sh);
    const float invW = 1.f / kD;
    float m1 = r4.x * invW, r1 = rsqrtf(r4.y * invW - m1 * m1 + kEPS);
    float m2 = r4.z * invW, r2 = rsqrtf(r4.w * invW - m2 * m2 + kEPS);
    float h0, h1v, h2v, h3;
    ld4h(HG + row * kD + c, h0, h1v, h2v, h3);
    float4 pv = *reinterpret_cast<const float4*>(prev + row * kD + c);
    float t0 = tanhf(g_h[c + 0] * ((ax - m1) * r1) + b_h[c + 0] +
                     g_c[c + 0] * ((dx - m2) * r2) + b_c[c + 0]);
    float t1 = tanhf(g_h[c + 1] * ((ay - m1) * r1) + b_h[c + 1] +
                     g_c[c + 1] * ((dy - m2) * r2) + b_c[c + 1]);
    float t2 = tanhf(g_h[c + 2] * ((az - m1) * r1) + b_h[c + 2] +
                     g_c[c + 2] * ((dz - m2) * r2) + b_c[c + 2]);
    float t3 = tanhf(g_h[c + 3] * ((aw - m1) * r1) + b_h[c + 3] +
                     g_c[c + 3] * ((dw - m2) * r2) + b_c[c + 3]);
    float4 o;
    o.x = (1.f - h0)  * t0 + h0  * pv.x;
    o.y = (1.f - h1v) * t1 + h1v * pv.y;
    o.z = (1.f - h2v) * t2 + h2v * pv.z;
    o.w = (1.f - h3)  * t3 + h3  * pv.w;
    *reinterpret_cast<float4*>(out + row * kD + c) = o;
}

// ---------------------------------------------------------------------------
// Launch
// ---------------------------------------------------------------------------
extern "C" void kernel_launch(void* const* d_in, const int* in_sizes, int n_in,
                              void* d_out, int out_size)
{
    int i_prev = -1, i_enc = -1, i_hidden = -1, i_ml = -1, i_Win = -1;
    int w4[4] = {-1, -1, -1, -1}; int n4 = 0;
    int p2[2] = {-1, -1};         int np = 0;
    int v8[8] = {-1, -1, -1, -1, -1, -1, -1, -1}; int nv = 0;
    for (int i = 0; i < n_in; i++) {
        switch (in_sizes[i]) {
            case 8388608: if (i_prev < 0) i_prev = i; else i_enc = i; break;
            case 16384:   i_hidden = i; break;
            case 32:      i_ml = i; break;
            case 786432:  i_Win = i; break;
            case 262144:  if (n4 < 4) w4[n4++] = i; break;
            case 1536:    if (np < 2) p2[np++] = i; break;
            case 512:     if (nv < 8) v8[nv++] = i; break;
            default: break;
        }
    }
    const float* prev   = (const float*)d_in[i_prev];
    const float* hidden = (const float*)d_in[i_hidden];
    const float* enc    = (const float*)d_in[i_enc];
    const int*   mlen   = (const int*)d_in[i_ml];
    const float* W_in   = (const float*)d_in[i_Win];
    const float* W_enc  = (const float*)d_in[w4[0]];
    const float* W_att  = (const float*)d_in[w4[1]];
    const float* W_hid  = (const float*)d_in[w4[2]];
    const float* W_ctx  = (const float*)d_in[w4[3]];
    const float* g_pre  = (const float*)d_in[p2[0]];
    const float* b_pre  = (const float*)d_in[p2[1]];
    const float* g_enc  = (const float*)d_in[v8[0]];
    const float* b_enc  = (const float*)d_in[v8[1]];
    const float* g_att  = (const float*)d_in[v8[2]];
    const float* b_att  = (const float*)d_in[v8[3]];
    const float* g_h    = (const float*)d_in[v8[4]];
    const float* b_h    = (const float*)d_in[v8[5]];
    const float* g_c    = (const float*)d_in[v8[6]];
    const float* b_c    = (const float*)d_in[v8[7]];

    float* sf = nullptr;
    __half* sh = nullptr;
    cudaGetSymbolAddress((void**)&sf, g_scf);
    cudaGetSymbolAddress((void**)&sh, g_sch);

    float* out       = (float*)d_out;            // [T,B,D]
    float* out_hid   = out + kTBD;               // [B,D]
    float* out_pattn = out_hid + (long)kB * kD;  // [T,B,S]

    cudaFuncSetAttribute(gemm_h_kernel,
                         cudaFuncAttributeMaxDynamicSharedMemorySize, GEMM_SMEM);

    dim3 tb(32, 8);
    const float invsq = rsqrtf((float)kD);
    const long bDS = (long)kB * kD;

    cudaStream_t s1;
    cudaStreamCreateWithFlags(&s1, cudaStreamNonBlocking);
    cudaEvent_t eW, eP, eQ, eS, eH;
    cudaEventCreateWithFlags(&eW, cudaEventDisableTiming);
    cudaEventCreateWithFlags(&eP, cudaEventDisableTiming);
    cudaEventCreateWithFlags(&eQ, cudaEventDisableTiming);
    cudaEventCreateWithFlags(&eS, cudaEventDisableTiming);
    cudaEventCreateWithFlags(&eH, cudaEventDisableTiming);

    // -- side stream: enc convert --
    f2h_kernel<<<8192, 256, 0, s1>>>(enc, sh + HF_ENC, kTBD / 4);

    // -- main: prev convert + weight transposes --
    f2h_kernel<<<8192, 256>>>(prev, sh + HF_PREV, kTBD / 4);
    transpose_f2h_kernel<<<dim3(16, 16, 3), tb>>>(W_in, sh + HF_WTIN, kD, 3 * kD,
                                                  512, (long)kD * kD);
    transpose4_f2h_kernel<<<dim3(16, 16, 4), tb>>>(W_enc, W_att, W_hid, W_ctx,
                                                   sh + HF_WTENC, sh + HF_WTATT,
                                                   sh + HF_WTHID, sh + HF_WTCTX);
    cudaEventRecord(eW, 0);

    // -- side stream: enc chain + pcw = pctx @ W_ctx (reassociated) --
    cudaStreamWaitEvent(s1, eW, 0);
    gemm_h_kernel<<<dim3(4, 128, 1), 256, GEMM_SMEM, s1>>>(
        sh + HF_ENC, sh + HF_WTENC, sh + HF_PCTXR, 512, 512, 512, 512, 0, 0, 0, 1.f);
    ln512h_kernel<<<(unsigned)kTB, 128, 0, s1>>>(sh + HF_PCTXR, sh + HF_PCTX,
                                                 g_enc, b_enc);
    cudaEventRecord(eP, s1);                     // pctx ready (score GEMM gate)
    gemm_h_kernel<<<dim3(4, 128, 1), 256, GEMM_SMEM, s1>>>(
        sh + HF_PCTX, sh + HF_WTCTX, sh + HF_PCW, 512, 512, 512, 512, 0, 0, 0, 1.f);
    transpose_h2h_kernel<<<dim3(16, 16, 32), tb, 0, s1>>>(
        sh + HF_PCW, sh + HF_PCWT, kS, kD, (long)kS * kD, (long)kD * kS);
    cudaEventRecord(eQ, s1);                     // pcwT ready (h2 GEMM gate)

    // -- main: preact chain --
    gemm_h_kernel<<<dim3(12, 128, 1), 256, GEMM_SMEM>>>(
        sh + HF_PREV, sh + HF_WTIN, sh + HF_PRE, 512, 512, 512, 1536, 0, 0, 0, 1.f);
    ln_preact_kernel<<<(unsigned)kTB, 384>>>(sh + HF_PRE, g_pre, b_pre,
                                             sh + HF_Z, sh + HF_HG, sh + HF_PL);
    scan_kernel<<<128, 64>>>(reinterpret_cast<__half2*>(sh + HF_Z),
                             reinterpret_cast<__half2*>(sh + HF_PL), hidden,
                             reinterpret_cast<__half2*>(sh + HF_SS), sf);
    cudaEventRecord(eS, 0);
    gemm_h_kernel<<<dim3(4, 128, 1), 256, GEMM_SMEM>>>(
        sh + HF_SS, sh + HF_WTATT, sh + HF_ATTR, 512, 512, 512, 512, 0, 0, 0, 1.f);
    ln512h_kernel<<<(unsigned)kTB, 128>>>(sh + HF_ATTR, sh + HF_ATT, g_att, b_att);

    // -- side stream: h1 = ss @ W_hidden --
    cudaStreamWaitEvent(s1, eS, 0);
    gemm_h_kernel<<<dim3(4, 128, 1), 256, GEMM_SMEM, s1>>>(
        sh + HF_SS, sh + HF_WTHID, sh + HF_H1, 512, 512, 512, 512, 0, 0, 0, 1.f);
    cudaEventRecord(eH, s1);

    // -- main: attention chain --
    cudaStreamWaitEvent(0, eP, 0);
    gemm_h_kernel<<<dim3(4, 4, 32), 256, GEMM_SMEM>>>(
        sh + HF_ATT, sh + HF_PCTX, sh + HF_SC, 512,
        bDS, 512, 512, kD, (long)kS * kD, (long)kT * kS, invsq);
    softmax_kernel<<<(unsigned)(kB * kT), 128>>>(sh + HF_SC, sh + HF_AV,
                                                 out_pattn, mlen);
    // h2 = av @ pcwT / sqrt(d)   (single GEMM, writes H2 directly)
    cudaStreamWaitEvent(0, eQ, 0);
    gemm_h_kernel<<<dim3(4, 4, 32), 256, GEMM_SMEM>>>(
        sh + HF_AV, sh + HF_PCWT, sh + HF_H2, 512,
        512, 512, bDS, (long)kT * kS, (long)kD * kS, kD, invsq);

    // join h1, final blend
    cudaStreamWaitEvent(0, eH, 0);
    final_kernel<<<(unsigned)kTB, 128>>>(sh + HF_H1, sh + HF_H2, sh + HF_HG, prev,
                                         g_h, b_h, g_c, b_c, out);
    cudaMemcpyAsync(out_hid, sf, (size_t)kB * kD * sizeof(float),
                    cudaMemcpyDeviceToDevice, 0);
    // (stream/events intentionally leaked: destroying mid-capture invalidates it)
}